// round 4
// baseline (speedup 1.0000x reference)
#include <cuda_runtime.h>

// Haar DWT2: input [8, 32, 512, 512] f32 -> output [8, 4, 32, 256, 256] f32.
// Subbands stacked at axis 1: (LL, LH, HL, HH).
//
// Per row-pair: 128 threads, thread i loads float4 at col 4*i of rows 2h2 and
// 2h2+1 (fully coalesced 512B/warp/load). Each thread computes a float2 per
// subband (output pixels 2i, 2i+1). Adjacent lanes combine via shfl so even
// lanes store a dense float4 per subband (256B/warp/subband, fully dense).

#define H 512
#define W 512
#define H2 256
#define W2 256
#define CCH 32                  // channels
#define PLANE_IN (H * W)        // 262144
#define PLANE_OUT (H2 * W2)     // 65536

__global__ __launch_bounds__(256) void haar_dwt2_kernel(
    const float* __restrict__ in, float* __restrict__ out)
{
    const int t   = threadIdx.x;           // 0..255
    const int i   = t & 127;               // 0..127 : float4-col index within row
    const int hr  = t >> 7;                // 0..1   : which row-pair in this block
    const int h2  = blockIdx.x * 2 + hr;   // 0..255
    const int bc  = blockIdx.y;            // 0..255 : b*32 + c
    const int b   = bc >> 5;
    const int c   = bc & 31;

    const float* src = in + (size_t)bc * PLANE_IN + (size_t)(2 * h2) * W + 4 * i;
    const float4 r0 = __ldcs(reinterpret_cast<const float4*>(src));
    const float4 r1 = __ldcs(reinterpret_cast<const float4*>(src + W));

    // pywt haar: LL=(a+b+c+d)/2, LH=(a+b-c-d)/2, HL=(a-b+c-d)/2, HH=(a-b-c+d)/2
    float2 LL, LH, HL, HH;
    {
        const float a = r0.x, bb = r0.y, cc = r1.x, dd = r1.y;
        LL.x = (a + bb + cc + dd) * 0.5f;
        LH.x = (a + bb - cc - dd) * 0.5f;
        HL.x = (a - bb + cc - dd) * 0.5f;
        HH.x = (a - bb - cc + dd) * 0.5f;
    }
    {
        const float a = r0.z, bb = r0.w, cc = r1.z, dd = r1.w;
        LL.y = (a + bb + cc + dd) * 0.5f;
        LH.y = (a + bb - cc - dd) * 0.5f;
        HL.y = (a - bb + cc - dd) * 0.5f;
        HH.y = (a - bb - cc + dd) * 0.5f;
    }

    // Lane pairing: even lane e takes odd lane e+1's float2 -> float4 for
    // output cols [4*(i/2) .. 4*(i/2)+3].
    const unsigned FULL = 0xFFFFFFFFu;
    float4 vLL, vLH, vHL, vHH;
    vLL.x = LL.x; vLL.y = LL.y;
    vLH.x = LH.x; vLH.y = LH.y;
    vHL.x = HL.x; vHL.y = HL.y;
    vHH.x = HH.x; vHH.y = HH.y;
    vLL.z = __shfl_xor_sync(FULL, LL.x, 1); vLL.w = __shfl_xor_sync(FULL, LL.y, 1);
    vLH.z = __shfl_xor_sync(FULL, LH.x, 1); vLH.w = __shfl_xor_sync(FULL, LH.y, 1);
    vHL.z = __shfl_xor_sync(FULL, HL.x, 1); vHL.w = __shfl_xor_sync(FULL, HL.y, 1);
    vHH.z = __shfl_xor_sync(FULL, HH.x, 1); vHH.w = __shfl_xor_sync(FULL, HH.y, 1);

    if ((i & 1) == 0) {
        // out layout: [b][s][c][h2][w2] with s in {0:LL,1:LH,2:HL,3:HH}
        const size_t base = ((size_t)(b * 4) * CCH + c) * PLANE_OUT
                            + (size_t)h2 * W2 + 2 * i;   // 2*i == 4*(i/2)
        float* o = out + base;
        const size_t sstride = (size_t)CCH * PLANE_OUT;  // subband group stride
        __stcs(reinterpret_cast<float4*>(o), vLL);
        __stcs(reinterpret_cast<float4*>(o + sstride), vLH);
        __stcs(reinterpret_cast<float4*>(o + 2 * sstride), vHL);
        __stcs(reinterpret_cast<float4*>(o + 3 * sstride), vHH);
    }
}

extern "C" void kernel_launch(void* const* d_in, const int* in_sizes, int n_in,
                              void* d_out, int out_size)
{
    const float* in = (const float*)d_in[0];
    float* out = (float*)d_out;
    dim3 grid(H2 / 2, 8 * CCH);   // (128 row-pair groups, 256 b*c planes)
    haar_dwt2_kernel<<<grid, 256>>>(in, out);
}

// round 5
// speedup vs baseline: 1.0753x; 1.0753x over previous
#include <cuda_runtime.h>

// Haar DWT2: input [8, 32, 512, 512] f32 -> output [8, 4, 32, 256, 256] f32.
// Subbands stacked at axis 1: (LL, LH, HL, HH).
//
// Each thread processes a 4(row) x 4(col) input block -> 2 output rows x 2
// output pixels per subband. Loads: 4x float4, each fully coalesced
// (512B/warp, dense), all independent (MLP=4). Stores: 8x float2 streaming,
// coalesced per subband plane.

#define H 512
#define W 512
#define H2 256
#define W2 256
#define CCH 32                  // channels
#define PLANE_IN (H * W)        // 262144
#define PLANE_OUT (H2 * W2)     // 65536

__device__ __forceinline__ void haar4(float a, float b, float c, float d,
                                      float& ll, float& lh, float& hl, float& hh)
{
    ll = (a + b + c + d) * 0.5f;
    lh = (a + b - c - d) * 0.5f;
    hl = (a - b + c - d) * 0.5f;
    hh = (a - b - c + d) * 0.5f;
}

__global__ __launch_bounds__(128) void haar_dwt2_kernel(
    const float* __restrict__ in, float* __restrict__ out)
{
    const int i   = threadIdx.x;           // 0..127 : float4-col index
    const int hq  = blockIdx.x;            // 0..127 : group of 2 output rows
    const int bc  = blockIdx.y;            // 0..255 : b*32 + c
    const int b   = bc >> 5;
    const int c   = bc & 31;
    const int h2  = 2 * hq;                // first output row of this block

    const float* src = in + (size_t)bc * PLANE_IN + (size_t)(4 * hq) * W + 4 * i;
    // 4 independent fully-coalesced loads (MLP=4), streaming.
    const float4 r0 = __ldcs(reinterpret_cast<const float4*>(src));
    const float4 r1 = __ldcs(reinterpret_cast<const float4*>(src + W));
    const float4 r2 = __ldcs(reinterpret_cast<const float4*>(src + 2 * W));
    const float4 r3 = __ldcs(reinterpret_cast<const float4*>(src + 3 * W));

    // pywt haar: LL=(a+b+c+d)/2, LH=(a+b-c-d)/2, HL=(a-b+c-d)/2, HH=(a-b-c+d)/2
    float2 LL0, LH0, HL0, HH0;   // output row h2
    float2 LL1, LH1, HL1, HH1;   // output row h2+1
    haar4(r0.x, r0.y, r1.x, r1.y, LL0.x, LH0.x, HL0.x, HH0.x);
    haar4(r0.z, r0.w, r1.z, r1.w, LL0.y, LH0.y, HL0.y, HH0.y);
    haar4(r2.x, r2.y, r3.x, r3.y, LL1.x, LH1.x, HL1.x, HH1.x);
    haar4(r2.z, r2.w, r3.z, r3.w, LL1.y, LH1.y, HL1.y, HH1.y);

    // out layout: [b][s][c][h2][w2] with s in {0:LL,1:LH,2:HL,3:HH}
    const size_t base = ((size_t)(b * 4) * CCH + c) * PLANE_OUT
                        + (size_t)h2 * W2 + 2 * i;
    float* o = out + base;
    const size_t sstride = (size_t)CCH * PLANE_OUT;  // subband group stride
    __stcs(reinterpret_cast<float2*>(o),                 LL0);
    __stcs(reinterpret_cast<float2*>(o + W2),            LL1);
    __stcs(reinterpret_cast<float2*>(o + sstride),       LH0);
    __stcs(reinterpret_cast<float2*>(o + sstride + W2),  LH1);
    __stcs(reinterpret_cast<float2*>(o + 2 * sstride),       HL0);
    __stcs(reinterpret_cast<float2*>(o + 2 * sstride + W2),  HL1);
    __stcs(reinterpret_cast<float2*>(o + 3 * sstride),       HH0);
    __stcs(reinterpret_cast<float2*>(o + 3 * sstride + W2),  HH1);
}

extern "C" void kernel_launch(void* const* d_in, const int* in_sizes, int n_in,
                              void* d_out, int out_size)
{
    const float* in = (const float*)d_in[0];
    float* out = (float*)d_out;
    dim3 grid(H2 / 2, 8 * CCH);   // (128 quad-row groups, 256 b*c planes)
    haar_dwt2_kernel<<<grid, 128>>>(in, out);
}